// round 12
// baseline (speedup 1.0000x reference)
#include <cuda_runtime.h>
#include <cuda_bf16.h>
#include <cuda_fp8.h>
#include <cstdint>

// ---------------------------------------------------------------------------
// Problem constants
// ---------------------------------------------------------------------------
#define N_ROWS 16384
#define K_ROWS 2048
#define D_DIM  1024

#define BM 128
#define BN 64
#define BK 128                  // fp8 -> 128 B per smem row (SW128 atom)
#define KT_PER_TILE 8           // D / BK
#define NTILES 4096             // (N/BM) * (K/BN) = 128 * 32
#define TN 32                   // tiles along n
#define GRID_P 444              // persistent CTAs (3 per SM)
#define STAGES 3
#define A_STAGE_BYTES (BM * 128)                      // 16 KB
#define B_STAGE_BYTES (BN * 128)                      //  8 KB
#define STAGE_BYTES (A_STAGE_BYTES + B_STAGE_BYTES)   // 24 KB
#define SM_ALLOC (STAGES * STAGE_BYTES)               // 72 KB -> 3 CTAs/SM

// fp8 mirrors + squared norms (device globals: allocation-free scratch)
// feat scaled by 2 (exact), cent scaled by 256 (exact):
//   acc = 512*feat.cent -> out = fs + cs - acc/256
__device__ uint8_t g_feat_f8[(size_t)N_ROWS * D_DIM];   // 16 MB
__device__ uint8_t g_cent_f8[(size_t)K_ROWS * D_DIM];   //  2 MB
__device__ float g_feat_sq[N_ROWS];
__device__ float g_cent_sq[K_ROWS];

// ---------------------------------------------------------------------------
// helpers
// ---------------------------------------------------------------------------
__device__ __forceinline__ void cp_async16(uint32_t saddr, const void* gaddr) {
    asm volatile("cp.async.cg.shared.global [%0], [%1], 16;" :: "r"(saddr), "l"(gaddr));
}

__device__ __forceinline__ void ldsm_x4(uint32_t* r, uint32_t addr) {
    asm volatile("ldmatrix.sync.aligned.m8n8.x4.shared.b16 {%0,%1,%2,%3}, [%4];"
                 : "=r"(r[0]), "=r"(r[1]), "=r"(r[2]), "=r"(r[3]) : "r"(addr));
}

__device__ __forceinline__ void mma_fp8(float* c, const uint32_t* a,
                                        uint32_t b0, uint32_t b1) {
    asm volatile(
        "mma.sync.aligned.m16n8k32.row.col.f32.e4m3.e4m3.f32 "
        "{%0,%1,%2,%3}, {%4,%5,%6,%7}, {%8,%9}, {%0,%1,%2,%3};\n"
        : "+f"(c[0]), "+f"(c[1]), "+f"(c[2]), "+f"(c[3])
        : "r"(a[0]), "r"(a[1]), "r"(a[2]), "r"(a[3]), "r"(b0), "r"(b1));
}

__device__ __forceinline__ void mbar_wait(uint32_t mbar, uint32_t parity) {
    uint32_t done;
    asm volatile(
        "{\n\t.reg .pred p;\n\t"
        "mbarrier.try_wait.parity.acquire.cta.shared::cta.b64 p, [%1], %2;\n\t"
        "selp.b32 %0, 1, 0, p;\n\t}"
        : "=r"(done) : "r"(mbar), "r"(parity) : "memory");
    if (!done) {
        asm volatile(
            "{\n\t.reg .pred P1;\n\t"
            "WL_%=:\n\t"
            "mbarrier.try_wait.parity.acquire.cta.shared::cta.b64 P1, [%0], %1, 0x989680;\n\t"
            "@P1 bra.uni WD_%=;\n\t"
            "bra.uni WL_%=;\n\t"
            "WD_%=:\n\t}"
            :: "r"(mbar), "r"(parity) : "memory");
    }
}

// ---------------------------------------------------------------------------
// fp32 -> fp8 conversion fused with row squared-norms. One warp per row.
// ---------------------------------------------------------------------------
__global__ void convert_norms_kernel(const float* __restrict__ feat,
                                     const float* __restrict__ cent) {
    int grow = blockIdx.x * 8 + (threadIdx.x >> 5);
    int lane = threadIdx.x & 31;
    const float* src;
    uint8_t* dst;
    float* sq;
    int row;
    float scale;
    if (grow < N_ROWS) { src = feat; dst = g_feat_f8; sq = g_feat_sq; row = grow; scale = 2.f; }
    else               { src = cent; dst = g_cent_f8; sq = g_cent_sq; row = grow - N_ROWS; scale = 256.f; }

    const float4* p = reinterpret_cast<const float4*>(src) + (size_t)row * (D_DIM / 4);
    uint32_t* d = reinterpret_cast<uint32_t*>(dst + (size_t)row * D_DIM);
    float s = 0.f;
#pragma unroll
    for (int i = lane; i < D_DIM / 4; i += 32) {
        float4 v = p[i];
        s += v.x * v.x + v.y * v.y + v.z * v.z + v.w * v.w;
        float2 lo = make_float2(v.x * scale, v.y * scale);
        float2 hi = make_float2(v.z * scale, v.w * scale);
        uint16_t plo = __nv_cvt_float2_to_fp8x2(lo, __NV_SATFINITE, __NV_E4M3);
        uint16_t phi = __nv_cvt_float2_to_fp8x2(hi, __NV_SATFINITE, __NV_E4M3);
        d[i] = (uint32_t)plo | ((uint32_t)phi << 16);
    }
#pragma unroll
    for (int o = 16; o > 0; o >>= 1) s += __shfl_xor_sync(0xffffffffu, s, o);
    if (lane == 0) sq[row] = s;
}

// ---------------------------------------------------------------------------
// Persistent FP8 distance GEMM, free-running warps, 3 CTAs/SM.
// Warp tile 32x32 (acc = 16 regs) so 24 warps/SM fit the 64K register file.
// 8 warps (4 M x 2 N) cover the 128x64 block tile.
// ---------------------------------------------------------------------------
__global__ void __launch_bounds__(256, 3)
dist_gemm_kernel(float* __restrict__ out) {
    extern __shared__ __align__(1024) char smem[];
    __shared__ __align__(8) uint64_t mbars[2 * STAGES];   // [full0..2, empty0..2]
    const uint32_t smem_u = (uint32_t)__cvta_generic_to_shared(smem);
    const uint32_t mb_u   = (uint32_t)__cvta_generic_to_shared(mbars);

    const int tid  = threadIdx.x;
    const int warp = tid >> 5;
    const int lane = tid & 31;
    const int bid  = blockIdx.x;

    const int wm = (warp & 3) * 32;    // warp M offset: 0/32/64/96
    const int wn = (warp >> 2) * 32;   // warp N offset: 0/32

    if (tid == 0) {
#pragma unroll
        for (int s = 0; s < STAGES; s++) {
            asm volatile("mbarrier.init.shared.b64 [%0], 256;"
                         :: "r"(mb_u + s * 8) : "memory");                 // full
            asm volatile("mbarrier.init.shared.b64 [%0], 8;"
                         :: "r"(mb_u + (STAGES + s) * 8) : "memory");      // empty
        }
    }
    __syncthreads();

    // --- producer mapping ---
    // A: 1024 chunks of 16B -> 4 per thread; B: 512 chunks -> 2 per thread
    const int a_row = tid >> 1;
    const int a_q0  = (tid & 1) * 4;
    const int b_row = tid >> 2;
    const int b_q0  = (tid & 3) * 2;
    uint32_t so_a[4], so_b[2];
    {
        const uint32_t arx = (a_row & 7) << 4;
        const uint32_t brx = (b_row & 7) << 4;
#pragma unroll
        for (int j = 0; j < 4; j++)
            so_a[j] = a_row * 128 + ((((a_q0 + j) * 16) ^ arx));
#pragma unroll
        for (int j = 0; j < 2; j++)
            so_b[j] = A_STAGE_BYTES + b_row * 128 + ((((b_q0 + j) * 16) ^ brx));
    }

    // incremental producer source pointers
    int p_t  = bid;
    int p_kt = 0;
    const uint8_t* ag = g_feat_f8 + (size_t)(((p_t >> 5) << 7) + a_row) * D_DIM + a_q0 * 16;
    const uint8_t* bg = g_cent_f8 + (size_t)(((p_t & (TN - 1)) << 6) + b_row) * D_DIM + b_q0 * 16;

    auto produce = [&](int s) {
        const uint32_t sb = smem_u + s * STAGE_BYTES;
#pragma unroll
        for (int j = 0; j < 4; j++)
            cp_async16(sb + so_a[j], ag + j * 16);
#pragma unroll
        for (int j = 0; j < 2; j++)
            cp_async16(sb + so_b[j], bg + j * 16);
        asm volatile("cp.async.mbarrier.arrive.noinc.shared::cta.b64 [%0];"
                     :: "r"(mb_u + s * 8) : "memory");
        if (++p_kt == KT_PER_TILE) {
            p_kt = 0;
            p_t += GRID_P;
            ag = g_feat_f8 + (size_t)(((p_t >> 5) << 7) + a_row) * D_DIM + a_q0 * 16;
            bg = g_cent_f8 + (size_t)(((p_t & (TN - 1)) << 6) + b_row) * D_DIM + b_q0 * 16;
        } else {
            ag += BK;
            bg += BK;
        }
    };

    // --- consumer addressing (constant parts) ---
    const int fr_lo = lane & 15;
    const uint32_t fr_hi16 = (lane >> 4) * 16;

    uint32_t a_rowb[2], a_rx[2], b_rowb[2], b_rx[2];
#pragma unroll
    for (int im = 0; im < 2; im++) {
        int r = wm + im * 16 + fr_lo;
        a_rowb[im] = r * 128;
        a_rx[im]   = (r & 7) << 4;
    }
#pragma unroll
    for (int ib = 0; ib < 2; ib++) {
        int r = wn + ib * 16 + fr_lo;
        b_rowb[ib] = A_STAGE_BYTES + r * 128;
        b_rx[ib]   = (r & 7) << 4;
    }

    float acc[2][4][4] = {};   // warp tile 32x32

    const int ntiles = (NTILES - bid + GRID_P - 1) / GRID_P;
    const int nsteps = ntiles * KT_PER_TILE;

    int ps = 0, pph = 1;
    int cs = 0, cph = 0;
    int c_t = bid;

    // prologue: fill STAGES-1 stages
#pragma unroll
    for (int k = 0; k < STAGES - 1; k++) {
        mbar_wait(mb_u + (STAGES + ps) * 8, (uint32_t)pph);
        produce(ps);
        if (++ps == STAGES) { ps = 0; pph ^= 1; }
    }

    for (int st = 0; st < nsteps; st++) {
        mbar_wait(mb_u + cs * 8, (uint32_t)cph);
        const uint32_t sbase = smem_u + cs * STAGE_BYTES;

#pragma unroll
        for (int ks = 0; ks < 4; ks++) {
            const uint32_t kb = ks * 32 + fr_hi16;
            uint32_t a[2][4], bq[2][4];
#pragma unroll
            for (int im = 0; im < 2; im++)
                ldsm_x4(a[im], sbase + a_rowb[im] + (kb ^ a_rx[im]));
#pragma unroll
            for (int ib = 0; ib < 2; ib++)
                ldsm_x4(bq[ib], sbase + b_rowb[ib] + (kb ^ b_rx[ib]));
#pragma unroll
            for (int im = 0; im < 2; im++) {
#pragma unroll
                for (int ib = 0; ib < 2; ib++) {
                    mma_fp8(acc[im][2 * ib],     a[im], bq[ib][0], bq[ib][2]);
                    mma_fp8(acc[im][2 * ib + 1], a[im], bq[ib][1], bq[ib][3]);
                }
            }
        }

        if (lane == 0) {
            asm volatile("mbarrier.arrive.shared.b64 _, [%0];"
                         :: "r"(mb_u + (STAGES + cs) * 8) : "memory");
        }
        if (++cs == STAGES) { cs = 0; cph ^= 1; }

        if (st + STAGES - 1 < nsteps) {
            mbar_wait(mb_u + (STAGES + ps) * 8, (uint32_t)pph);
            produce(ps);
            if (++ps == STAGES) { ps = 0; pph ^= 1; }
        }

        if ((st & 7) == 7) {
            // ---- epilogue for finished tile; ring stays warm ----
            const int m0 = (c_t >> 5) << 7;
            const int n0 = (c_t & (TN - 1)) << 6;
            c_t += GRID_P;
            const float inv = 1.0f / 256.0f;
            const int g = lane >> 2;
            const int tt = lane & 3;
#pragma unroll
            for (int im = 0; im < 2; im++) {
                int gm = m0 + wm + im * 16 + g;
                float fs0 = g_feat_sq[gm];
                float fs1 = g_feat_sq[gm + 8];
#pragma unroll
                for (int in = 0; in < 4; in++) {
                    int gn = n0 + wn + in * 8 + 2 * tt;
                    float cs0 = g_cent_sq[gn];
                    float cs1 = g_cent_sq[gn + 1];
                    float2 v0, v1;
                    v0.x = fs0 + cs0 - acc[im][in][0] * inv;
                    v0.y = fs0 + cs1 - acc[im][in][1] * inv;
                    v1.x = fs1 + cs0 - acc[im][in][2] * inv;
                    v1.y = fs1 + cs1 - acc[im][in][3] * inv;
                    *reinterpret_cast<float2*>(out + (size_t)gm * K_ROWS + gn)       = v0;
                    *reinterpret_cast<float2*>(out + (size_t)(gm + 8) * K_ROWS + gn) = v1;
                }
            }
#pragma unroll
            for (int im = 0; im < 2; im++)
#pragma unroll
                for (int in = 0; in < 4; in++)
#pragma unroll
                    for (int c = 0; c < 4; c++)
                        acc[im][in][c] = 0.f;
        }
    }
}

// ---------------------------------------------------------------------------
extern "C" void kernel_launch(void* const* d_in, const int* in_sizes, int n_in,
                              void* d_out, int out_size) {
    const float* feat = (const float*)d_in[0];
    const float* cent = (const float*)d_in[1];
    float* out = (float*)d_out;

    cudaFuncSetAttribute(dist_gemm_kernel,
                         cudaFuncAttributeMaxDynamicSharedMemorySize, SM_ALLOC);

    convert_norms_kernel<<<(N_ROWS + K_ROWS) / 8, 256>>>(feat, cent);

    dist_gemm_kernel<<<GRID_P, 256, SM_ALLOC>>>(out);
}

// round 13
// speedup vs baseline: 1.0302x; 1.0302x over previous
#include <cuda_runtime.h>
#include <cuda_bf16.h>
#include <cuda_fp8.h>
#include <cstdint>

// ---------------------------------------------------------------------------
// Problem constants
// ---------------------------------------------------------------------------
#define N_ROWS 16384
#define K_ROWS 2048
#define D_DIM  1024

#define BM 128
#define BN 128
#define BK 128                  // fp8 -> 128 B per smem row (SW128 atom)
#define KT_PER_TILE 8           // D / BK
#define NTILES 2048             // (N/BM) * (K/BN)
#define TN 16                   // tiles along n
#define GRID_P 296              // persistent CTAs (2 per SM)
#define STAGES 3
#define A_STAGE_BYTES (BM * 128)                      // 16 KB
#define B_STAGE_BYTES (BN * 128)                      // 16 KB
#define STAGE_BYTES (A_STAGE_BYTES + B_STAGE_BYTES)   // 32 KB
#define SM_ALLOC (STAGES * STAGE_BYTES)               // 96 KB -> 2 CTAs/SM

// fp8 mirrors + squared norms (device globals: allocation-free scratch)
// feat scaled by 2 (exact), cent scaled by 256 (exact):
//   acc = 512*feat.cent -> out = fs + cs - acc/256
__device__ uint8_t g_feat_f8[(size_t)N_ROWS * D_DIM];   // 16 MB
__device__ uint8_t g_cent_f8[(size_t)K_ROWS * D_DIM];   //  2 MB
__device__ float g_feat_sq[N_ROWS];
__device__ float g_cent_sq[K_ROWS];

// ---------------------------------------------------------------------------
// helpers
// ---------------------------------------------------------------------------
__device__ __forceinline__ void cp_async16(uint32_t saddr, const void* gaddr) {
    asm volatile("cp.async.cg.shared.global [%0], [%1], 16;" :: "r"(saddr), "l"(gaddr));
}

__device__ __forceinline__ void ldsm_x4(uint32_t* r, uint32_t addr) {
    asm volatile("ldmatrix.sync.aligned.m8n8.x4.shared.b16 {%0,%1,%2,%3}, [%4];"
                 : "=r"(r[0]), "=r"(r[1]), "=r"(r[2]), "=r"(r[3]) : "r"(addr));
}

__device__ __forceinline__ void mma_fp8(float* c, const uint32_t* a,
                                        uint32_t b0, uint32_t b1) {
    asm volatile(
        "mma.sync.aligned.m16n8k32.row.col.f32.e4m3.e4m3.f32 "
        "{%0,%1,%2,%3}, {%4,%5,%6,%7}, {%8,%9}, {%0,%1,%2,%3};\n"
        : "+f"(c[0]), "+f"(c[1]), "+f"(c[2]), "+f"(c[3])
        : "r"(a[0]), "r"(a[1]), "r"(a[2]), "r"(a[3]), "r"(b0), "r"(b1));
}

__device__ __forceinline__ void mbar_wait(uint32_t mbar, uint32_t parity) {
    uint32_t done;
    asm volatile(
        "{\n\t.reg .pred p;\n\t"
        "mbarrier.try_wait.parity.acquire.cta.shared::cta.b64 p, [%1], %2;\n\t"
        "selp.b32 %0, 1, 0, p;\n\t}"
        : "=r"(done) : "r"(mbar), "r"(parity) : "memory");
    if (!done) {
        asm volatile(
            "{\n\t.reg .pred P1;\n\t"
            "WL_%=:\n\t"
            "mbarrier.try_wait.parity.acquire.cta.shared::cta.b64 P1, [%0], %1, 0x989680;\n\t"
            "@P1 bra.uni WD_%=;\n\t"
            "bra.uni WL_%=;\n\t"
            "WD_%=:\n\t}"
            :: "r"(mbar), "r"(parity) : "memory");
    }
}

// ---------------------------------------------------------------------------
// fp32 -> fp8 conversion fused with row squared-norms. One warp per row.
// ---------------------------------------------------------------------------
__global__ void convert_norms_kernel(const float* __restrict__ feat,
                                     const float* __restrict__ cent) {
    int grow = blockIdx.x * 8 + (threadIdx.x >> 5);
    int lane = threadIdx.x & 31;
    const float* src;
    uint8_t* dst;
    float* sq;
    int row;
    float scale;
    if (grow < N_ROWS) { src = feat; dst = g_feat_f8; sq = g_feat_sq; row = grow; scale = 2.f; }
    else               { src = cent; dst = g_cent_f8; sq = g_cent_sq; row = grow - N_ROWS; scale = 256.f; }

    const float4* p = reinterpret_cast<const float4*>(src) + (size_t)row * (D_DIM / 4);
    uint32_t* d = reinterpret_cast<uint32_t*>(dst + (size_t)row * D_DIM);
    float s = 0.f;
#pragma unroll
    for (int i = lane; i < D_DIM / 4; i += 32) {
        float4 v = p[i];
        s += v.x * v.x + v.y * v.y + v.z * v.z + v.w * v.w;
        float2 lo = make_float2(v.x * scale, v.y * scale);
        float2 hi = make_float2(v.z * scale, v.w * scale);
        uint16_t plo = __nv_cvt_float2_to_fp8x2(lo, __NV_SATFINITE, __NV_E4M3);
        uint16_t phi = __nv_cvt_float2_to_fp8x2(hi, __NV_SATFINITE, __NV_E4M3);
        d[i] = (uint32_t)plo | ((uint32_t)phi << 16);
    }
#pragma unroll
    for (int o = 16; o > 0; o >>= 1) s += __shfl_xor_sync(0xffffffffu, s, o);
    if (lane == 0) sq[row] = s;
}

// ---------------------------------------------------------------------------
// Persistent FP8 distance GEMM, free-running warps, 2 CTAs/SM (R10 base).
// NEW: CUTLASS-style early stage release — all 24 LDSM issue within the first
// two MMA bursts (2-deep fragment buffer), then __syncwarp + lane0 arrives on
// empty[s] BEFORE the last two MMA bursts, so the producer refills ~2 bursts
// earlier each step.
// ---------------------------------------------------------------------------
__global__ void __launch_bounds__(256, 2)
dist_gemm_kernel(float* __restrict__ out) {
    extern __shared__ __align__(1024) char smem[];
    __shared__ __align__(8) uint64_t mbars[2 * STAGES];   // [full0..2, empty0..2]
    const uint32_t smem_u = (uint32_t)__cvta_generic_to_shared(smem);
    const uint32_t mb_u   = (uint32_t)__cvta_generic_to_shared(mbars);

    const int tid  = threadIdx.x;
    const int warp = tid >> 5;
    const int lane = tid & 31;
    const int bid  = blockIdx.x;

    const int wm = (warp >> 2) * 64;
    const int wn = (warp & 3) * 32;

    if (tid == 0) {
#pragma unroll
        for (int s = 0; s < STAGES; s++) {
            asm volatile("mbarrier.init.shared.b64 [%0], 256;"
                         :: "r"(mb_u + s * 8) : "memory");                 // full
            asm volatile("mbarrier.init.shared.b64 [%0], 8;"
                         :: "r"(mb_u + (STAGES + s) * 8) : "memory");      // empty
        }
    }
    __syncthreads();

    // --- producer constants ---
    const int ld_row = tid >> 1;
    const int ld_q0  = (tid & 1) * 4;
    const uint32_t ld_rx = (ld_row & 7) << 4;
    uint32_t so[4];
#pragma unroll
    for (int j = 0; j < 4; j++)
        so[j] = ld_row * 128 + ((((ld_q0 + j) * 16) ^ ld_rx));

    int p_t  = bid;
    int p_kt = 0;
    const uint8_t* ag = g_feat_f8 + (size_t)(((p_t >> 4) << 7) + ld_row) * D_DIM + ld_q0 * 16;
    const uint8_t* bg = g_cent_f8 + (size_t)(((p_t & (TN - 1)) << 7) + ld_row) * D_DIM + ld_q0 * 16;

    auto produce = [&](int s) {
        const uint32_t abase = smem_u + s * STAGE_BYTES;
        const uint32_t bbase = abase + A_STAGE_BYTES;
#pragma unroll
        for (int j = 0; j < 4; j++) {
            cp_async16(abase + so[j], ag + j * 16);
            cp_async16(bbase + so[j], bg + j * 16);
        }
        asm volatile("cp.async.mbarrier.arrive.noinc.shared::cta.b64 [%0];"
                     :: "r"(mb_u + s * 8) : "memory");
        if (++p_kt == KT_PER_TILE) {
            p_kt = 0;
            p_t += GRID_P;
            ag = g_feat_f8 + (size_t)(((p_t >> 4) << 7) + ld_row) * D_DIM + ld_q0 * 16;
            bg = g_cent_f8 + (size_t)(((p_t & (TN - 1)) << 7) + ld_row) * D_DIM + ld_q0 * 16;
        } else {
            ag += BK;
            bg += BK;
        }
    };

    // --- consumer addressing (constant parts) ---
    const int fr_lo = lane & 15;
    const uint32_t fr_hi16 = (lane >> 4) * 16;

    uint32_t a_rowb[4], a_rx[4], b_rowb[2], b_rx[2];
#pragma unroll
    for (int im = 0; im < 4; im++) {
        int r = wm + im * 16 + fr_lo;
        a_rowb[im] = r * 128;
        a_rx[im]   = (r & 7) << 4;
    }
#pragma unroll
    for (int ib = 0; ib < 2; ib++) {
        int r = wn + ib * 16 + fr_lo;
        b_rowb[ib] = A_STAGE_BYTES + r * 128;
        b_rx[ib]   = (r & 7) << 4;
    }

    float acc[4][4][4] = {};
    uint32_t afr[2][4][4], bfr[2][2][4];   // 2-deep fragment buffer

    auto ld_frags = [&](int buf, uint32_t sbase, int ks) {
        const uint32_t kb = ks * 32 + fr_hi16;
#pragma unroll
        for (int im = 0; im < 4; im++)
            ldsm_x4(afr[buf][im], sbase + a_rowb[im] + (kb ^ a_rx[im]));
#pragma unroll
        for (int ib = 0; ib < 2; ib++)
            ldsm_x4(bfr[buf][ib], sbase + b_rowb[ib] + (kb ^ b_rx[ib]));
    };
    auto do_mma = [&](int buf) {
#pragma unroll
        for (int im = 0; im < 4; im++) {
#pragma unroll
            for (int ib = 0; ib < 2; ib++) {
                mma_fp8(acc[im][2 * ib],     afr[buf][im], bfr[buf][ib][0], bfr[buf][ib][2]);
                mma_fp8(acc[im][2 * ib + 1], afr[buf][im], bfr[buf][ib][1], bfr[buf][ib][3]);
            }
        }
    };

    const int ntiles = (NTILES - bid + GRID_P - 1) / GRID_P;
    const int nsteps = ntiles * KT_PER_TILE;

    int ps = 0, pph = 1;
    int cs = 0, cph = 0;
    int c_t = bid;

#pragma unroll
    for (int k = 0; k < STAGES - 1; k++) {
        mbar_wait(mb_u + (STAGES + ps) * 8, (uint32_t)pph);
        produce(ps);
        if (++ps == STAGES) { ps = 0; pph ^= 1; }
    }

    for (int st = 0; st < nsteps; st++) {
        mbar_wait(mb_u + cs * 8, (uint32_t)cph);
        const uint32_t sbase = smem_u + cs * STAGE_BYTES;

        // --- software-pipelined k-steps with EARLY stage release ---
        ld_frags(0, sbase, 0);
        ld_frags(1, sbase, 1);
        do_mma(0);                    // ks0
        ld_frags(0, sbase, 2);
        do_mma(1);                    // ks1
        ld_frags(1, sbase, 3);        // last smem read of this stage
        __syncwarp();                 // order all lanes' reads before release
        if (lane == 0) {
            asm volatile("mbarrier.arrive.shared.b64 _, [%0];"
                         :: "r"(mb_u + (STAGES + cs) * 8) : "memory");
        }
        do_mma(0);                    // ks2
        do_mma(1);                    // ks3

        if (++cs == STAGES) { cs = 0; cph ^= 1; }

        if (st + STAGES - 1 < nsteps) {
            mbar_wait(mb_u + (STAGES + ps) * 8, (uint32_t)pph);
            produce(ps);
            if (++ps == STAGES) { ps = 0; pph ^= 1; }
        }

        if ((st & 7) == 7) {
            // ---- epilogue for finished tile; ring stays warm ----
            const int m0 = (c_t >> 4) << 7;
            const int n0 = (c_t & (TN - 1)) << 7;
            c_t += GRID_P;
            const float inv = 1.0f / 256.0f;
            const int g = lane >> 2;
            const int tt = lane & 3;
#pragma unroll
            for (int im = 0; im < 4; im++) {
                int gm = m0 + wm + im * 16 + g;
                float fs0 = g_feat_sq[gm];
                float fs1 = g_feat_sq[gm + 8];
#pragma unroll
                for (int in = 0; in < 4; in++) {
                    int gn = n0 + wn + in * 8 + 2 * tt;
                    float cs0 = g_cent_sq[gn];
                    float cs1 = g_cent_sq[gn + 1];
                    float2 v0, v1;
                    v0.x = fs0 + cs0 - acc[im][in][0] * inv;
                    v0.y = fs0 + cs1 - acc[im][in][1] * inv;
                    v1.x = fs1 + cs0 - acc[im][in][2] * inv;
                    v1.y = fs1 + cs1 - acc[im][in][3] * inv;
                    *reinterpret_cast<float2*>(out + (size_t)gm * K_ROWS + gn)       = v0;
                    *reinterpret_cast<float2*>(out + (size_t)(gm + 8) * K_ROWS + gn) = v1;
                }
            }
#pragma unroll
            for (int im = 0; im < 4; im++)
#pragma unroll
                for (int in = 0; in < 4; in++)
#pragma unroll
                    for (int c = 0; c < 4; c++)
                        acc[im][in][c] = 0.f;
        }
    }
}

// ---------------------------------------------------------------------------
extern "C" void kernel_launch(void* const* d_in, const int* in_sizes, int n_in,
                              void* d_out, int out_size) {
    const float* feat = (const float*)d_in[0];
    const float* cent = (const float*)d_in[1];
    float* out = (float*)d_out;

    cudaFuncSetAttribute(dist_gemm_kernel,
                         cudaFuncAttributeMaxDynamicSharedMemorySize, SM_ALLOC);

    convert_norms_kernel<<<(N_ROWS + K_ROWS) / 8, 256>>>(feat, cent);

    dist_gemm_kernel<<<GRID_P, 256, SM_ALLOC>>>(out);
}

// round 14
// speedup vs baseline: 1.0495x; 1.0187x over previous
#include <cuda_runtime.h>
#include <cuda_bf16.h>
#include <cuda_fp8.h>
#include <cstdint>

// ---------------------------------------------------------------------------
// Problem constants
// ---------------------------------------------------------------------------
#define N_ROWS 16384
#define K_ROWS 2048
#define D_DIM  1024

#define BM 128
#define BN 128
#define BK 128                  // fp8 -> 128 B per smem row (SW128 atom)
#define KT_PER_TILE 8           // D / BK
#define NTILES 2048             // (N/BM) * (K/BN)
#define TN 16                   // tiles along n
#define GRID_P 296              // persistent CTAs (2 per SM)
#define STAGES 3
#define A_STAGE_BYTES (BM * 128)                      // 16 KB
#define B_STAGE_BYTES (BN * 128)                      // 16 KB
#define STAGE_BYTES (A_STAGE_BYTES + B_STAGE_BYTES)   // 32 KB
#define SM_ALLOC (STAGES * STAGE_BYTES)               // 96 KB -> 2 CTAs/SM

// fp8 mirrors + squared norms (device globals: allocation-free scratch)
// feat scaled by 2 (exact), cent scaled by 256 (exact):
//   acc = 512*feat.cent -> out = fs + cs - acc/256
__device__ uint8_t g_feat_f8[(size_t)N_ROWS * D_DIM];   // 16 MB
__device__ uint8_t g_cent_f8[(size_t)K_ROWS * D_DIM];   //  2 MB
__device__ float g_feat_sq[N_ROWS];
__device__ float g_cent_sq[K_ROWS];

// ---------------------------------------------------------------------------
// helpers
// ---------------------------------------------------------------------------
__device__ __forceinline__ void cp_async16(uint32_t saddr, const void* gaddr) {
    asm volatile("cp.async.cg.shared.global [%0], [%1], 16;" :: "r"(saddr), "l"(gaddr));
}

__device__ __forceinline__ void ldsm_x4(uint32_t* r, uint32_t addr) {
    asm volatile("ldmatrix.sync.aligned.m8n8.x4.shared.b16 {%0,%1,%2,%3}, [%4];"
                 : "=r"(r[0]), "=r"(r[1]), "=r"(r[2]), "=r"(r[3]) : "r"(addr));
}

__device__ __forceinline__ void mma_fp8(float* c, const uint32_t* a,
                                        uint32_t b0, uint32_t b1) {
    asm volatile(
        "mma.sync.aligned.m16n8k32.row.col.f32.e4m3.e4m3.f32 "
        "{%0,%1,%2,%3}, {%4,%5,%6,%7}, {%8,%9}, {%0,%1,%2,%3};\n"
        : "+f"(c[0]), "+f"(c[1]), "+f"(c[2]), "+f"(c[3])
        : "r"(a[0]), "r"(a[1]), "r"(a[2]), "r"(a[3]), "r"(b0), "r"(b1));
}

__device__ __forceinline__ void mbar_wait(uint32_t mbar, uint32_t parity) {
    uint32_t done;
    asm volatile(
        "{\n\t.reg .pred p;\n\t"
        "mbarrier.try_wait.parity.acquire.cta.shared::cta.b64 p, [%1], %2;\n\t"
        "selp.b32 %0, 1, 0, p;\n\t}"
        : "=r"(done) : "r"(mbar), "r"(parity) : "memory");
    if (!done) {
        asm volatile(
            "{\n\t.reg .pred P1;\n\t"
            "WL_%=:\n\t"
            "mbarrier.try_wait.parity.acquire.cta.shared::cta.b64 P1, [%0], %1, 0x989680;\n\t"
            "@P1 bra.uni WD_%=;\n\t"
            "bra.uni WL_%=;\n\t"
            "WD_%=:\n\t}"
            :: "r"(mbar), "r"(parity) : "memory");
    }
}

// ---------------------------------------------------------------------------
// fp32 -> fp8 conversion fused with row squared-norms. One warp per row.
// Each lane handles 2 adjacent 16B chunks per iter -> coalesced STG.64 out.
// feat scaled by 2, cent scaled by 256 (both exact powers of two).
// ---------------------------------------------------------------------------
__global__ void __launch_bounds__(512, 2)
convert_norms_kernel(const float* __restrict__ feat,
                     const float* __restrict__ cent) {
    int grow = blockIdx.x * 16 + (threadIdx.x >> 5);
    int lane = threadIdx.x & 31;
    const float* src;
    uint8_t* dst;
    float* sq;
    int row;
    float scale;
    if (grow < N_ROWS) { src = feat; dst = g_feat_f8; sq = g_feat_sq; row = grow; scale = 2.f; }
    else               { src = cent; dst = g_cent_f8; sq = g_cent_sq; row = grow - N_ROWS; scale = 256.f; }

    const float4* p = reinterpret_cast<const float4*>(src) + (size_t)row * (D_DIM / 4);
    uint2* d = reinterpret_cast<uint2*>(dst + (size_t)row * D_DIM);
    float s = 0.f;
#pragma unroll
    for (int it = 0; it < 4; it++) {
        int c = it * 64 + lane * 2;            // chunk pair: c, c+1
        float4 v0 = p[c];
        float4 v1 = p[c + 1];
        s += v0.x * v0.x + v0.y * v0.y + v0.z * v0.z + v0.w * v0.w;
        s += v1.x * v1.x + v1.y * v1.y + v1.z * v1.z + v1.w * v1.w;
        uint16_t a0 = __nv_cvt_float2_to_fp8x2(make_float2(v0.x * scale, v0.y * scale),
                                               __NV_SATFINITE, __NV_E4M3);
        uint16_t a1 = __nv_cvt_float2_to_fp8x2(make_float2(v0.z * scale, v0.w * scale),
                                               __NV_SATFINITE, __NV_E4M3);
        uint16_t a2 = __nv_cvt_float2_to_fp8x2(make_float2(v1.x * scale, v1.y * scale),
                                               __NV_SATFINITE, __NV_E4M3);
        uint16_t a3 = __nv_cvt_float2_to_fp8x2(make_float2(v1.z * scale, v1.w * scale),
                                               __NV_SATFINITE, __NV_E4M3);
        uint2 u;
        u.x = (uint32_t)a0 | ((uint32_t)a1 << 16);
        u.y = (uint32_t)a2 | ((uint32_t)a3 << 16);
        d[it * 32 + lane] = u;                 // STG.64, fully coalesced
    }
#pragma unroll
    for (int o = 16; o > 0; o >>= 1) s += __shfl_xor_sync(0xffffffffu, s, o);
    if (lane == 0) sq[row] = s;
}

// ---------------------------------------------------------------------------
// Persistent FP8 distance GEMM (R9 proven-best mainloop, verbatim).
// Free-running warps, 2 CTAs/SM, per-warp ks rotation, warm ring across tiles.
// ---------------------------------------------------------------------------
__global__ void __launch_bounds__(256, 2)
dist_gemm_kernel(float* __restrict__ out) {
    extern __shared__ __align__(1024) char smem[];
    __shared__ __align__(8) uint64_t mbars[2 * STAGES];   // [full0..2, empty0..2]
    const uint32_t smem_u = (uint32_t)__cvta_generic_to_shared(smem);
    const uint32_t mb_u   = (uint32_t)__cvta_generic_to_shared(mbars);

    const int tid  = threadIdx.x;
    const int warp = tid >> 5;
    const int lane = tid & 31;
    const int bid  = blockIdx.x;

    const int wm = (warp >> 2) * 64;
    const int wn = (warp & 3) * 32;

    if (tid == 0) {
#pragma unroll
        for (int s = 0; s < STAGES; s++) {
            asm volatile("mbarrier.init.shared.b64 [%0], 256;"
                         :: "r"(mb_u + s * 8) : "memory");                 // full
            asm volatile("mbarrier.init.shared.b64 [%0], 8;"
                         :: "r"(mb_u + (STAGES + s) * 8) : "memory");      // empty
        }
    }
    __syncthreads();

    // --- producer addressing ---
    const int ld_row = tid >> 1;
    const int ld_q0  = (tid & 1) * 4;
    const uint32_t ld_sw_row = ld_row * 128;
    const uint32_t ld_rx     = (ld_row & 7) << 4;

    auto produce = [&](int s, int st) {
        const int t  = bid + (st >> 3) * GRID_P;
        const int kt = st & 7;
        const int m0 = (t >> 4) << 7;
        const int n0 = (t & (TN - 1)) << 7;
        const uint32_t abase = smem_u + s * STAGE_BYTES;
        const uint32_t bbase = abase + A_STAGE_BYTES;
        const uint8_t* ag = g_feat_f8 + (size_t)(m0 + ld_row) * D_DIM + kt * BK + ld_q0 * 16;
        const uint8_t* bg = g_cent_f8 + (size_t)(n0 + ld_row) * D_DIM + kt * BK + ld_q0 * 16;
#pragma unroll
        for (int j = 0; j < 4; j++) {
            uint32_t so = ld_sw_row + ((((ld_q0 + j) * 16) ^ ld_rx));
            cp_async16(abase + so, ag + j * 16);
            cp_async16(bbase + so, bg + j * 16);
        }
        asm volatile("cp.async.mbarrier.arrive.noinc.shared::cta.b64 [%0];"
                     :: "r"(mb_u + s * 8) : "memory");
    };

    // --- consumer addressing (constant parts) ---
    const int fr_lo = lane & 15;
    const uint32_t fr_hi16 = (lane >> 4) * 16;

    uint32_t a_rowb[4], a_rx[4], b_rowb[2], b_rx[2];
#pragma unroll
    for (int im = 0; im < 4; im++) {
        int r = wm + im * 16 + fr_lo;
        a_rowb[im] = r * 128;
        a_rx[im]   = (r & 7) << 4;
    }
#pragma unroll
    for (int ib = 0; ib < 2; ib++) {
        int r = wn + ib * 16 + fr_lo;
        b_rowb[ib] = r * 128;
        b_rx[ib]   = (r & 7) << 4;
    }

    float acc[4][4][4] = {};

    const int ntiles = (NTILES - bid + GRID_P - 1) / GRID_P;
    const int nsteps = ntiles * KT_PER_TILE;

    int ps = 0, pph = 1;
    int cs = 0, cph = 0;

#pragma unroll
    for (int k = 0; k < STAGES - 1; k++) {
        mbar_wait(mb_u + (STAGES + ps) * 8, (uint32_t)pph);
        produce(ps, k);
        if (++ps == STAGES) { ps = 0; pph ^= 1; }
    }

    for (int st = 0; st < nsteps; st++) {
        mbar_wait(mb_u + cs * 8, (uint32_t)cph);
        const uint32_t abase = smem_u + cs * STAGE_BYTES;
        const uint32_t bbase = abase + A_STAGE_BYTES;

#pragma unroll
        for (int ks = 0; ks < 4; ks++) {
            const int kse = (ks + warp) & 3;
            const uint32_t kb = kse * 32 + fr_hi16;
            uint32_t a[4][4], bq[2][4];
#pragma unroll
            for (int im = 0; im < 4; im++)
                ldsm_x4(a[im], abase + a_rowb[im] + (kb ^ a_rx[im]));
#pragma unroll
            for (int ib = 0; ib < 2; ib++)
                ldsm_x4(bq[ib], bbase + b_rowb[ib] + (kb ^ b_rx[ib]));
#pragma unroll
            for (int im = 0; im < 4; im++) {
#pragma unroll
                for (int ib = 0; ib < 2; ib++) {
                    mma_fp8(acc[im][2 * ib],     a[im], bq[ib][0], bq[ib][2]);
                    mma_fp8(acc[im][2 * ib + 1], a[im], bq[ib][1], bq[ib][3]);
                }
            }
        }

        if (lane == 0) {
            asm volatile("mbarrier.arrive.shared.b64 _, [%0];"
                         :: "r"(mb_u + (STAGES + cs) * 8) : "memory");
        }
        if (++cs == STAGES) { cs = 0; cph ^= 1; }

        if (st + STAGES - 1 < nsteps) {
            mbar_wait(mb_u + (STAGES + ps) * 8, (uint32_t)pph);
            produce(ps, st + STAGES - 1);
            if (++ps == STAGES) { ps = 0; pph ^= 1; }
        }

        if ((st & 7) == 7) {
            // ---- epilogue for finished tile; ring stays warm ----
            const int t  = bid + (st >> 3) * GRID_P;
            const int m0 = (t >> 4) << 7;
            const int n0 = (t & (TN - 1)) << 7;
            const float inv = 1.0f / 256.0f;
            const int g = lane >> 2;
            const int tt = lane & 3;
#pragma unroll
            for (int im = 0; im < 4; im++) {
                int gm = m0 + wm + im * 16 + g;
                float fs0 = g_feat_sq[gm];
                float fs1 = g_feat_sq[gm + 8];
#pragma unroll
                for (int in = 0; in < 4; in++) {
                    int gn = n0 + wn + in * 8 + 2 * tt;
                    float cs0 = g_cent_sq[gn];
                    float cs1 = g_cent_sq[gn + 1];
                    float2 v0, v1;
                    v0.x = fs0 + cs0 - acc[im][in][0] * inv;
                    v0.y = fs0 + cs1 - acc[im][in][1] * inv;
                    v1.x = fs1 + cs0 - acc[im][in][2] * inv;
                    v1.y = fs1 + cs1 - acc[im][in][3] * inv;
                    *reinterpret_cast<float2*>(out + (size_t)gm * K_ROWS + gn)       = v0;
                    *reinterpret_cast<float2*>(out + (size_t)(gm + 8) * K_ROWS + gn) = v1;
                }
            }
#pragma unroll
            for (int im = 0; im < 4; im++)
#pragma unroll
                for (int in = 0; in < 4; in++)
#pragma unroll
                    for (int c = 0; c < 4; c++)
                        acc[im][in][c] = 0.f;
        }
    }
}

// ---------------------------------------------------------------------------
extern "C" void kernel_launch(void* const* d_in, const int* in_sizes, int n_in,
                              void* d_out, int out_size) {
    const float* feat = (const float*)d_in[0];
    const float* cent = (const float*)d_in[1];
    float* out = (float*)d_out;

    cudaFuncSetAttribute(dist_gemm_kernel,
                         cudaFuncAttributeMaxDynamicSharedMemorySize, SM_ALLOC);

    convert_norms_kernel<<<(N_ROWS + K_ROWS) / 16, 512>>>(feat, cent);

    dist_gemm_kernel<<<GRID_P, 256, SM_ALLOC>>>(out);
}